// round 1
// baseline (speedup 1.0000x reference)
#include <cuda_runtime.h>
#include <cstdint>

// Sinkhorn-Knopp, non-log domain.
//   E = exp(-C/gamma), gamma=0.1  -> E = exp(-10*C), E in [4.5e-5, 1]
//   50 x { eu = (d+eps)/(E ev);  ev = (s+eps)/(E^T eu) },  ev0 = exp(1)
//   P = eu_i * E_ij * ev_j
// All fp32. Pure streaming GEMV passes -> HBM-bound.

#define NN 8192
#define N4 (NN / 4)              // 2048 float4 per row
#define NSTRIPES 64
#define ROWS_PER_STRIPE (NN / NSTRIPES)   // 128
#define EPS 1e-6f

// Static device scratch (allocation-free rule: __device__ globals only)
__device__ float g_E[(size_t)NN * NN];       // 256 MB
__device__ float g_eu[NN];
__device__ float g_ev[NN];
__device__ float g_part[NSTRIPES * NN];      // 2 MB column partials

// ---------------------------------------------------------------------------
// Fast exp for x in [-15, 0]: FMA-only (no MUFU) so precompute stays HBM-bound.
// exp(x) = 2^(x*log2e); n = rint(t), f = t-n in [-0.5,0.5]; degree-6 Taylor of
// 2^f (rel err ~1e-7); scale by exponent-field construction (n >= -15 -> safe).
// ---------------------------------------------------------------------------
__device__ __forceinline__ float fast_exp_neg(float x) {
    const float LOG2E = 1.4426950408889634f;
    float t = x * LOG2E;
    float n = rintf(t);
    float f = t - n;
    // 2^f Taylor coefficients: ln2^k / k!
    float p = 1.5403530393381608e-4f;
    p = fmaf(p, f, 1.3333558146428443e-3f);
    p = fmaf(p, f, 9.6181291076284770e-3f);
    p = fmaf(p, f, 5.5504108664821580e-2f);
    p = fmaf(p, f, 2.4022650695910070e-1f);
    p = fmaf(p, f, 6.9314718055994530e-1f);
    p = fmaf(p, f, 1.0f);
    int e = (int)n;
    float scale = __int_as_float((e + 127) << 23);
    return p * scale;
}

// ---------------------------------------------------------------------------
// Precompute E = exp(-10*C); also init ev = exp(1).
// grid covers 16M float4 elements.
// ---------------------------------------------------------------------------
__global__ void precompute_kernel(const float* __restrict__ C) {
    size_t i4 = (size_t)blockIdx.x * blockDim.x + threadIdx.x;
    const float4* C4 = reinterpret_cast<const float4*>(C);
    float4* E4 = reinterpret_cast<float4*>(g_E);
    if (i4 < (size_t)NN * N4) {
        float4 c = C4[i4];
        float4 e;
        e.x = fast_exp_neg(-10.0f * c.x);
        e.y = fast_exp_neg(-10.0f * c.y);
        e.z = fast_exp_neg(-10.0f * c.z);
        e.w = fast_exp_neg(-10.0f * c.w);
        E4[i4] = e;
    }
    if (i4 < NN) {
        g_ev[i4] = 2.718281828459045f;  // exp(v0) with v0 = 1
    }
}

// ---------------------------------------------------------------------------
// Row pass: eu_i = (d_i + eps) / sum_j E[i][j] * ev[j]
// One warp per row; float4 streaming loads; warp shfl reduction.
// ---------------------------------------------------------------------------
__global__ void row_kernel(const float* __restrict__ d) {
    int warp = blockIdx.x * (blockDim.x >> 5) + (threadIdx.x >> 5);
    int lane = threadIdx.x & 31;
    if (warp >= NN) return;
    const float4* Erow = reinterpret_cast<const float4*>(g_E + (size_t)warp * NN);
    const float4* ev4 = reinterpret_cast<const float4*>(g_ev);
    float acc = 0.0f;
#pragma unroll 8
    for (int j = lane; j < N4; j += 32) {
        float4 e = Erow[j];
        float4 v = ev4[j];   // 32KB, L1-resident after first touch
        acc += e.x * v.x + e.y * v.y + e.z * v.z + e.w * v.w;
    }
#pragma unroll
    for (int o = 16; o > 0; o >>= 1)
        acc += __shfl_down_sync(0xFFFFFFFFu, acc, o);
    if (lane == 0)
        g_eu[warp] = (d[warp] + EPS) / acc;
}

// ---------------------------------------------------------------------------
// Column pass, phase 1: per-stripe partial column sums (deterministic,
// no atomics). grid = (NN/(256*4), NSTRIPES) = (8, 64), 256 threads.
// Each thread owns 4 columns (one float4 lane) over 128 rows.
// ---------------------------------------------------------------------------
__global__ void col_partial_kernel() {
    int col4 = blockIdx.x * blockDim.x + threadIdx.x;   // 0..2047
    int r0 = blockIdx.y * ROWS_PER_STRIPE;
    const float4* E4 = reinterpret_cast<const float4*>(g_E);
    float4 acc = make_float4(0.f, 0.f, 0.f, 0.f);
#pragma unroll 4
    for (int r = r0; r < r0 + ROWS_PER_STRIPE; ++r) {
        float u = g_eu[r];                          // warp-uniform broadcast
        float4 e = E4[(size_t)r * N4 + col4];
        acc.x = fmaf(e.x, u, acc.x);
        acc.y = fmaf(e.y, u, acc.y);
        acc.z = fmaf(e.z, u, acc.z);
        acc.w = fmaf(e.w, u, acc.w);
    }
    reinterpret_cast<float4*>(g_part)[(size_t)blockIdx.y * N4 + col4] = acc;
}

// ---------------------------------------------------------------------------
// Column pass, phase 2: reduce stripes, ev_j = (s_j + eps)/colsum_j.
// 8192 threads.
// ---------------------------------------------------------------------------
__global__ void col_reduce_kernel(const float* __restrict__ s) {
    int j = blockIdx.x * blockDim.x + threadIdx.x;
    if (j >= NN) return;
    float acc = 0.0f;
#pragma unroll
    for (int k = 0; k < NSTRIPES; ++k)
        acc += g_part[k * NN + j];
    g_ev[j] = (s[j] + EPS) / acc;
}

// ---------------------------------------------------------------------------
// Final: P_ij = eu_i * E_ij * ev_j
// ---------------------------------------------------------------------------
__global__ void final_kernel(float* __restrict__ out) {
    size_t i4 = (size_t)blockIdx.x * blockDim.x + threadIdx.x;
    if (i4 >= (size_t)NN * N4) return;
    int row = (int)(i4 / N4);
    int col4 = (int)(i4 % N4);
    float u = g_eu[row];
    float4 v = reinterpret_cast<const float4*>(g_ev)[col4];
    float4 e = reinterpret_cast<const float4*>(g_E)[i4];
    float4 p;
    p.x = u * e.x * v.x;
    p.y = u * e.y * v.y;
    p.z = u * e.z * v.z;
    p.w = u * e.w * v.w;
    reinterpret_cast<float4*>(out)[i4] = p;
}

// ---------------------------------------------------------------------------
extern "C" void kernel_launch(void* const* d_in, const int* in_sizes, int n_in,
                              void* d_out, int out_size) {
    const float* C = (const float*)d_in[0];
    const float* d = (const float*)d_in[1];
    const float* s = (const float*)d_in[2];
    float* out = (float*)d_out;

    const int total4 = NN * N4;              // 16M float4
    const int PRE_BLOCKS = total4 / 256;     // 65536

    precompute_kernel<<<PRE_BLOCKS, 256>>>(C);

    for (int it = 0; it < 50; ++it) {
        row_kernel<<<NN / 8, 256>>>(d);                      // 1024 CTAs, warp/row
        col_partial_kernel<<<dim3(N4 / 256, NSTRIPES), 256>>>();
        col_reduce_kernel<<<NN / 256, 256>>>(s);
    }

    final_kernel<<<PRE_BLOCKS, 256>>>(out);
}

// round 2
// speedup vs baseline: 1.3585x; 1.3585x over previous
#include <cuda_runtime.h>
#include <cuda_fp16.h>
#include <cstdint>

// Sinkhorn-Knopp, non-log domain, fp16 kernel matrix.
//   E' = 1024 * exp(-10*C)  stored as fp16 (all values normal: [0.046, 1024])
//   50 x { eu' = (d+eps)/(E' ev);  ev = (s+eps)/(E'^T eu') }
//   P = eu'_i * E'_ij * ev_j            (the 1024 scale cancels exactly)
// Hot loop streams 128MB fp16 per pass. L2 (~126MB) ping-pong: row pass
// descends rows, col pass ascends -> each pass starts on the previous
// pass's L2-resident tail.

#define NN 8192
#define N8 (NN / 8)                 // 1024 uint4 (8 halves) per row
#define NSTRIPES 64
#define ROWS_PER_STRIPE (NN / NSTRIPES)   // 128
#define EPS 1e-6f
#define ESCALE 1024.0f

__device__ __half g_E[(size_t)NN * NN];      // 128 MB
__device__ float  g_eu[NN];
__device__ float  g_ev[NN];
__device__ float  g_part[NSTRIPES * NN];     // 2 MB

// FMA-only exp for x in [-15, 0] (no MUFU -> precompute stays HBM-bound)
__device__ __forceinline__ float fast_exp_neg(float x) {
    const float LOG2E = 1.4426950408889634f;
    float t = x * LOG2E;
    float n = rintf(t);
    float f = t - n;
    float p = 1.5403530393381608e-4f;
    p = fmaf(p, f, 1.3333558146428443e-3f);
    p = fmaf(p, f, 9.6181291076284770e-3f);
    p = fmaf(p, f, 5.5504108664821580e-2f);
    p = fmaf(p, f, 2.4022650695910070e-1f);
    p = fmaf(p, f, 6.9314718055994530e-1f);
    p = fmaf(p, f, 1.0f);
    float scale = __int_as_float(((int)n + 127) << 23);
    return p * scale;
}

// ---------------------------------------------------------------------------
// Precompute E' = 1024*exp(-10*C) as fp16; init ev = exp(1). Forward stream.
// One thread per 8 elements.
// ---------------------------------------------------------------------------
__global__ void precompute_kernel(const float* __restrict__ C) {
    size_t g = (size_t)blockIdx.x * blockDim.x + threadIdx.x;   // 0 .. 8M-1
    const float4* C4 = reinterpret_cast<const float4*>(C);
    float4 c0 = C4[2 * g];
    float4 c1 = C4[2 * g + 1];
    __half2 h[4];
    h[0] = __floats2half2_rn(ESCALE * fast_exp_neg(-10.0f * c0.x),
                             ESCALE * fast_exp_neg(-10.0f * c0.y));
    h[1] = __floats2half2_rn(ESCALE * fast_exp_neg(-10.0f * c0.z),
                             ESCALE * fast_exp_neg(-10.0f * c0.w));
    h[2] = __floats2half2_rn(ESCALE * fast_exp_neg(-10.0f * c1.x),
                             ESCALE * fast_exp_neg(-10.0f * c1.y));
    h[3] = __floats2half2_rn(ESCALE * fast_exp_neg(-10.0f * c1.z),
                             ESCALE * fast_exp_neg(-10.0f * c1.w));
    reinterpret_cast<uint4*>(g_E)[g] = *reinterpret_cast<uint4*>(h);
    if (g < NN) g_ev[g] = 2.718281828459045f;   // exp(v0), v0 = 1
}

// ---------------------------------------------------------------------------
// Row pass (BACKWARD stream): eu'_i = (d_i+eps) / sum_j E'_ij ev_j
// One warp per row, rows processed in descending order across the grid.
// ---------------------------------------------------------------------------
__global__ void row_kernel(const float* __restrict__ d) {
    int wg   = blockIdx.x * (blockDim.x >> 5) + (threadIdx.x >> 5);
    int lane = threadIdx.x & 31;
    int row  = NN - 1 - wg;                       // descending
    const uint4*  Erow = reinterpret_cast<const uint4*>(g_E + (size_t)row * NN);
    const float4* ev4  = reinterpret_cast<const float4*>(g_ev);
    float acc = 0.0f;
#pragma unroll 4
    for (int j = lane; j < N8; j += 32) {
        uint4 e = Erow[j];
        const __half2* hp = reinterpret_cast<const __half2*>(&e);
        float4 v0 = ev4[2 * j];
        float4 v1 = ev4[2 * j + 1];
        float2 f0 = __half22float2(hp[0]);
        float2 f1 = __half22float2(hp[1]);
        float2 f2 = __half22float2(hp[2]);
        float2 f3 = __half22float2(hp[3]);
        acc = fmaf(f0.x, v0.x, acc); acc = fmaf(f0.y, v0.y, acc);
        acc = fmaf(f1.x, v0.z, acc); acc = fmaf(f1.y, v0.w, acc);
        acc = fmaf(f2.x, v1.x, acc); acc = fmaf(f2.y, v1.y, acc);
        acc = fmaf(f3.x, v1.z, acc); acc = fmaf(f3.y, v1.w, acc);
    }
#pragma unroll
    for (int o = 16; o > 0; o >>= 1)
        acc += __shfl_down_sync(0xFFFFFFFFu, acc, o);
    if (lane == 0)
        g_eu[row] = (d[row] + EPS) / acc;
}

// ---------------------------------------------------------------------------
// Col pass phase 1 (FORWARD stream): per-stripe partial column sums.
// grid = (N8/256, NSTRIPES); each thread owns 8 adjacent columns.
// ---------------------------------------------------------------------------
__global__ void col_partial_kernel() {
    int c8 = blockIdx.x * blockDim.x + threadIdx.x;   // 0..1023
    int r0 = blockIdx.y * ROWS_PER_STRIPE;
    const uint4* E8 = reinterpret_cast<const uint4*>(g_E);
    float4 a0 = make_float4(0.f, 0.f, 0.f, 0.f);
    float4 a1 = make_float4(0.f, 0.f, 0.f, 0.f);
#pragma unroll 4
    for (int r = r0; r < r0 + ROWS_PER_STRIPE; ++r) {
        float u = g_eu[r];                            // L1-resident broadcast
        uint4 e = E8[(size_t)r * N8 + c8];
        const __half2* hp = reinterpret_cast<const __half2*>(&e);
        float2 f0 = __half22float2(hp[0]);
        float2 f1 = __half22float2(hp[1]);
        float2 f2 = __half22float2(hp[2]);
        float2 f3 = __half22float2(hp[3]);
        a0.x = fmaf(f0.x, u, a0.x); a0.y = fmaf(f0.y, u, a0.y);
        a0.z = fmaf(f1.x, u, a0.z); a0.w = fmaf(f1.y, u, a0.w);
        a1.x = fmaf(f2.x, u, a1.x); a1.y = fmaf(f2.y, u, a1.y);
        a1.z = fmaf(f3.x, u, a1.z); a1.w = fmaf(f3.y, u, a1.w);
    }
    float4* P4 = reinterpret_cast<float4*>(g_part + (size_t)blockIdx.y * NN);
    P4[2 * c8]     = a0;
    P4[2 * c8 + 1] = a1;
}

// ---------------------------------------------------------------------------
// Col pass phase 2: reduce stripes, ev_j = (s_j+eps)/colsum_j.
// ---------------------------------------------------------------------------
__global__ void col_reduce_kernel(const float* __restrict__ s) {
    int j = blockIdx.x * blockDim.x + threadIdx.x;
    float acc = 0.0f;
#pragma unroll
    for (int k = 0; k < NSTRIPES; ++k)
        acc += g_part[k * NN + j];
    g_ev[j] = (s[j] + EPS) / acc;
}

// ---------------------------------------------------------------------------
// Final (BACKWARD stream): P_ij = eu'_i * E'_ij * ev_j
// ---------------------------------------------------------------------------
__global__ void final_kernel(float* __restrict__ out) {
    size_t g   = (size_t)blockIdx.x * blockDim.x + threadIdx.x;
    size_t idx = (size_t)NN * N8 - 1 - g;             // descending
    int row = (int)(idx / N8);
    int c8  = (int)(idx % N8);
    float u = g_eu[row];
    const float4* ev4 = reinterpret_cast<const float4*>(g_ev);
    float4 v0 = ev4[2 * c8];
    float4 v1 = ev4[2 * c8 + 1];
    uint4 e = reinterpret_cast<const uint4*>(g_E)[idx];
    const __half2* hp = reinterpret_cast<const __half2*>(&e);
    float2 f0 = __half22float2(hp[0]);
    float2 f1 = __half22float2(hp[1]);
    float2 f2 = __half22float2(hp[2]);
    float2 f3 = __half22float2(hp[3]);
    float4 p0, p1;
    p0.x = u * f0.x * v0.x;  p0.y = u * f0.y * v0.y;
    p0.z = u * f1.x * v0.z;  p0.w = u * f1.y * v0.w;
    p1.x = u * f2.x * v1.x;  p1.y = u * f2.y * v1.y;
    p1.z = u * f3.x * v1.z;  p1.w = u * f3.y * v1.w;
    float4* O4 = reinterpret_cast<float4*>(out);
    O4[2 * idx]     = p0;
    O4[2 * idx + 1] = p1;
}

// ---------------------------------------------------------------------------
extern "C" void kernel_launch(void* const* d_in, const int* in_sizes, int n_in,
                              void* d_out, int out_size) {
    const float* C = (const float*)d_in[0];
    const float* d = (const float*)d_in[1];
    const float* s = (const float*)d_in[2];
    float* out = (float*)d_out;

    const int total8 = NN * N8;                  // 8M vec8 elements
    const int VBLOCKS = total8 / 256;            // 32768

    precompute_kernel<<<VBLOCKS, 256>>>(C);      // forward

    for (int it = 0; it < 50; ++it) {
        row_kernel<<<NN / 8, 256>>>(d);                          // backward
        col_partial_kernel<<<dim3(N8 / 256, NSTRIPES), 256>>>(); // forward
        col_reduce_kernel<<<NN / 256, 256>>>(s);
    }

    final_kernel<<<VBLOCKS, 256>>>(out);         // backward
}

// round 3
// speedup vs baseline: 2.3429x; 1.7246x over previous
#include <cuda_runtime.h>
#include <cuda_fp16.h>
#include <cstdint>

// Sinkhorn-Knopp, fp16 kernel matrix, ONE DRAM sweep per iteration.
//   E' = 1024*exp(-10*C) in fp16 (normal range [0.046, 1024]; scale cancels)
//   iter: fused kernel streams E once:
//     phase 1 (per 32-row panel): eu_r = (d_r+eps) / sum_j E_rj ev_j
//     phase 2 (same CTA, panel re-read from L2): partial col sums with fresh eu
//   col_reduce: ev_j = (s_j+eps) / sum over 256 panel-partials (fixed order)
//   P = eu_i E'_ij ev_j

#define NN 8192
#define N8 (NN / 8)                  // 1024 uint4 (8 halves) per row
#define PROWS 32                     // rows per panel
#define NPANELS (NN / PROWS)         // 256
#define EPS 1e-6f
#define ESCALE 1024.0f

__device__ __half g_E[(size_t)NN * NN];      // 128 MB
__device__ float  g_eu[NN];
__device__ float  g_ev[NN];
__device__ float  g_part[(size_t)NPANELS * NN];   // 8 MB panel col-partials

// FMA-only exp for x in [-15, 0]
__device__ __forceinline__ float fast_exp_neg(float x) {
    const float LOG2E = 1.4426950408889634f;
    float t = x * LOG2E;
    float n = rintf(t);
    float f = t - n;
    float p = 1.5403530393381608e-4f;
    p = fmaf(p, f, 1.3333558146428443e-3f);
    p = fmaf(p, f, 9.6181291076284770e-3f);
    p = fmaf(p, f, 5.5504108664821580e-2f);
    p = fmaf(p, f, 2.4022650695910070e-1f);
    p = fmaf(p, f, 6.9314718055994530e-1f);
    p = fmaf(p, f, 1.0f);
    return p * __int_as_float(((int)n + 127) << 23);
}

// ---------------------------------------------------------------------------
__global__ void precompute_kernel(const float* __restrict__ C) {
    size_t g = (size_t)blockIdx.x * blockDim.x + threadIdx.x;
    const float4* C4 = reinterpret_cast<const float4*>(C);
    float4 c0 = C4[2 * g];
    float4 c1 = C4[2 * g + 1];
    __half2 h[4];
    h[0] = __floats2half2_rn(ESCALE * fast_exp_neg(-10.0f * c0.x),
                             ESCALE * fast_exp_neg(-10.0f * c0.y));
    h[1] = __floats2half2_rn(ESCALE * fast_exp_neg(-10.0f * c0.z),
                             ESCALE * fast_exp_neg(-10.0f * c0.w));
    h[2] = __floats2half2_rn(ESCALE * fast_exp_neg(-10.0f * c1.x),
                             ESCALE * fast_exp_neg(-10.0f * c1.y));
    h[3] = __floats2half2_rn(ESCALE * fast_exp_neg(-10.0f * c1.z),
                             ESCALE * fast_exp_neg(-10.0f * c1.w));
    reinterpret_cast<uint4*>(g_E)[g] = *reinterpret_cast<uint4*>(h);
    if (g < NN) g_ev[g] = 2.718281828459045f;     // exp(v0), v0 = 1
}

// ---------------------------------------------------------------------------
// Fused iteration kernel. grid = NPANELS (256) CTAs x 1024 threads.
// ---------------------------------------------------------------------------
__global__ void __launch_bounds__(1024, 1)
iter_kernel(const float* __restrict__ d) {
    __shared__ float eu_s[PROWS];
    const int tid  = threadIdx.x;
    const int wid  = tid >> 5;
    const int lane = tid & 31;
    const int panel = blockIdx.x;
    const int row0  = panel * PROWS;

    // ---------------- Phase 1: row sums (warp per row) ----------------
    {
        const int r = row0 + wid;
        const uint4*  Erow = reinterpret_cast<const uint4*>(g_E + (size_t)r * NN);
        const float4* ev4  = reinterpret_cast<const float4*>(g_ev);
        float a0 = 0.f, a1 = 0.f, a2 = 0.f, a3 = 0.f;
#pragma unroll 8
        for (int j = lane; j < N8; j += 32) {
            uint4 e = Erow[j];
            const __half2* hp = reinterpret_cast<const __half2*>(&e);
            float4 v0 = ev4[2 * j];
            float4 v1 = ev4[2 * j + 1];
            float2 f0 = __half22float2(hp[0]);
            float2 f1 = __half22float2(hp[1]);
            float2 f2 = __half22float2(hp[2]);
            float2 f3 = __half22float2(hp[3]);
            a0 = fmaf(f0.x, v0.x, a0); a0 = fmaf(f0.y, v0.y, a0);
            a1 = fmaf(f1.x, v0.z, a1); a1 = fmaf(f1.y, v0.w, a1);
            a2 = fmaf(f2.x, v1.x, a2); a2 = fmaf(f2.y, v1.y, a2);
            a3 = fmaf(f3.x, v1.z, a3); a3 = fmaf(f3.y, v1.w, a3);
        }
        float acc = (a0 + a1) + (a2 + a3);
#pragma unroll
        for (int o = 16; o > 0; o >>= 1)
            acc += __shfl_down_sync(0xFFFFFFFFu, acc, o);
        if (lane == 0) {
            float eu = (d[r] + EPS) / acc;
            eu_s[wid] = eu;
            g_eu[r] = eu;         // for the final kernel
        }
    }
    __syncthreads();

    // ---------------- Phase 2: panel column partials (re-read, L2-hot) ----
    {
        // thread t owns 8 columns [8t, 8t+8)
        const uint4* E8 = reinterpret_cast<const uint4*>(g_E) + (size_t)row0 * N8 + tid;
        float c0 = 0.f, c1 = 0.f, c2 = 0.f, c3 = 0.f;
        float c4 = 0.f, c5 = 0.f, c6 = 0.f, c7 = 0.f;
#pragma unroll 4
        for (int r = 0; r < PROWS; ++r) {
            float u = eu_s[r];
            uint4 e = E8[(size_t)r * N8];
            const __half2* hp = reinterpret_cast<const __half2*>(&e);
            float2 f0 = __half22float2(hp[0]);
            float2 f1 = __half22float2(hp[1]);
            float2 f2 = __half22float2(hp[2]);
            float2 f3 = __half22float2(hp[3]);
            c0 = fmaf(f0.x, u, c0); c1 = fmaf(f0.y, u, c1);
            c2 = fmaf(f1.x, u, c2); c3 = fmaf(f1.y, u, c3);
            c4 = fmaf(f2.x, u, c4); c5 = fmaf(f2.y, u, c5);
            c6 = fmaf(f3.x, u, c6); c7 = fmaf(f3.y, u, c7);
        }
        float4* P4 = reinterpret_cast<float4*>(g_part + (size_t)panel * NN);
        P4[2 * tid]     = make_float4(c0, c1, c2, c3);
        P4[2 * tid + 1] = make_float4(c4, c5, c6, c7);
    }
}

// ---------------------------------------------------------------------------
// Stripe reduction: ev_j = (s_j+eps) / sum_{k<256} part[k][j], fixed order.
// grid = 256 CTAs x 256 threads; CTA covers 32 columns, 8 k-groups.
// ---------------------------------------------------------------------------
__global__ void col_reduce_kernel(const float* __restrict__ s) {
    __shared__ float red[8][32];
    const int lane = threadIdx.x & 31;
    const int p    = threadIdx.x >> 5;          // 0..7
    const int j    = blockIdx.x * 32 + lane;
    float acc = 0.0f;
    const float* base = g_part + (size_t)(p * 32) * NN + j;
#pragma unroll 8
    for (int kk = 0; kk < 32; ++kk)
        acc += base[(size_t)kk * NN];
    red[p][lane] = acc;
    __syncthreads();
    if (p == 0) {
        float t = 0.0f;
#pragma unroll
        for (int q = 0; q < 8; ++q)             // fixed order -> deterministic
            t += red[q][lane];
        g_ev[j] = (s[j] + EPS) / t;
    }
}

// ---------------------------------------------------------------------------
// Final (backward stream): P_ij = eu_i * E'_ij * ev_j
// ---------------------------------------------------------------------------
__global__ void final_kernel(float* __restrict__ out) {
    size_t g   = (size_t)blockIdx.x * blockDim.x + threadIdx.x;
    size_t idx = (size_t)NN * N8 - 1 - g;
    int row = (int)(idx / N8);
    int c8  = (int)(idx % N8);
    float u = g_eu[row];
    const float4* ev4 = reinterpret_cast<const float4*>(g_ev);
    float4 v0 = ev4[2 * c8];
    float4 v1 = ev4[2 * c8 + 1];
    uint4 e = reinterpret_cast<const uint4*>(g_E)[idx];
    const __half2* hp = reinterpret_cast<const __half2*>(&e);
    float2 f0 = __half22float2(hp[0]);
    float2 f1 = __half22float2(hp[1]);
    float2 f2 = __half22float2(hp[2]);
    float2 f3 = __half22float2(hp[3]);
    float4 p0, p1;
    p0.x = u * f0.x * v0.x;  p0.y = u * f0.y * v0.y;
    p0.z = u * f1.x * v0.z;  p0.w = u * f1.y * v0.w;
    p1.x = u * f2.x * v1.x;  p1.y = u * f2.y * v1.y;
    p1.z = u * f3.x * v1.z;  p1.w = u * f3.y * v1.w;
    float4* O4 = reinterpret_cast<float4*>(out);
    O4[2 * idx]     = p0;
    O4[2 * idx + 1] = p1;
}

// ---------------------------------------------------------------------------
extern "C" void kernel_launch(void* const* d_in, const int* in_sizes, int n_in,
                              void* d_out, int out_size) {
    const float* C = (const float*)d_in[0];
    const float* d = (const float*)d_in[1];
    const float* s = (const float*)d_in[2];
    float* out = (float*)d_out;

    const int VBLOCKS = (NN * N8) / 256;     // 32768

    precompute_kernel<<<VBLOCKS, 256>>>(C);

    for (int it = 0; it < 50; ++it) {
        iter_kernel<<<NPANELS, 1024>>>(d);
        col_reduce_kernel<<<NN / 32, 256>>>(s);
    }

    final_kernel<<<VBLOCKS, 256>>>(out);
}